// round 5
// baseline (speedup 1.0000x reference)
#include <cuda_runtime.h>
#include <cuda_bf16.h>
#include <cstdint>

#define N_NODES 50000
#define N_EDGES 625000
#define C 128
#define SCAN_T 1024
#define SCAN_CH ((N_NODES + SCAN_T - 1) / SCAN_T)   // 49

// Scratch (__device__ globals; allocations are banned)
__device__ float g_y[(size_t)N_NODES * C];   // x @ W^T
__device__ float g_dis[N_NODES];             // deg^-1/2
__device__ float g_Wt[C * C];                // W transposed: g_Wt[k*C+o] = W[o*C+k]
__device__ int   g_row[N_EDGES];
__device__ int   g_col[N_EDGES];
__device__ int   g_cnt[N_NODES];             // degree counts
__device__ int   g_cur[N_NODES];             // fill cursors
__device__ int   g_off[N_NODES + 1];         // CSR offsets
__device__ int   g_ecol[N_EDGES];            // CSR column (src) ids
__device__ int   g_is64;

// ---------------------------------------------------------------------------
// packed f32x2 helpers (sm_103a FFMA2 path — ptxas only emits via PTX f32x2)
__device__ __forceinline__ unsigned long long bcast2(float f) {
    unsigned long long r;
    asm("mov.b64 %0, {%1, %1};" : "=l"(r) : "f"(f));
    return r;
}
__device__ __forceinline__ unsigned long long fma2(unsigned long long a,
                                                   unsigned long long b,
                                                   unsigned long long c) {
    unsigned long long d;
    asm("fma.rn.f32x2 %0, %1, %2, %3;" : "=l"(d) : "l"(a), "l"(b), "l"(c));
    return d;
}
__device__ __forceinline__ void unpack2(unsigned long long v, float& lo, float& hi) {
    asm("mov.b64 {%0, %1}, %2;" : "=f"(lo), "=f"(hi) : "l"(v));
}

// ---------------------------------------------------------------------------
__global__ void k_detect(const long long* __restrict__ ei) {
    __shared__ int ok;
    if (threadIdx.x == 0) ok = 1;
    __syncthreads();
    for (int i = threadIdx.x; i < 1024; i += blockDim.x) {
        long long v = ei[i];
        if (v < 0 || v >= N_NODES) atomicExch(&ok, 0);
    }
    __syncthreads();
    if (threadIdx.x == 0) g_is64 = ok;
}

// zero counters + transpose W (independent work fused into one launch)
__global__ void k_prep(const float* __restrict__ W) {
    int i = blockIdx.x * blockDim.x + threadIdx.x;
    if (i < N_NODES) { g_cnt[i] = 0; g_cur[i] = 0; }
    if (i < C * C) {
        int o = i >> 7, k = i & 127;
        g_Wt[k * C + o] = W[i];
    }
}

// normalize edges + count degrees in one pass
__global__ void k_edges(const void* __restrict__ ei) {
    int e = blockIdx.x * blockDim.x + threadIdx.x;
    if (e >= N_EDGES) return;
    int r, c;
    if (g_is64) {
        const long long* p = (const long long*)ei;
        r = (int)p[e];
        c = (int)p[e + N_EDGES];
    } else {
        const int* p = (const int*)ei;
        r = p[e];
        c = p[e + N_EDGES];
    }
    g_row[e] = r;
    g_col[e] = c;
    if ((unsigned)r < N_NODES) atomicAdd(&g_cnt[r], 1);
}

// Single-block exclusive scan over g_cnt -> g_off, plus deg^-1/2 -> g_dis
__global__ void __launch_bounds__(SCAN_T) k_scan_fin() {
    __shared__ int part[SCAN_T];
    const int t = threadIdx.x;
    const int base = t * SCAN_CH;
    int s = 0;
    for (int i = base; i < base + SCAN_CH && i < N_NODES; i++) s += g_cnt[i];
    part[t] = s;
    __syncthreads();
    for (int off = 1; off < SCAN_T; off <<= 1) {
        int v = (t >= off) ? part[t - off] : 0;
        __syncthreads();
        part[t] += v;
        __syncthreads();
    }
    int run = (t == 0) ? 0 : part[t - 1];
    for (int i = base; i < base + SCAN_CH && i < N_NODES; i++) {
        int d = g_cnt[i];
        g_off[i] = run;
        run += d;
        g_dis[i] = (d > 0) ? rsqrtf((float)d) : 0.f;
    }
    if (t == SCAN_T - 1) g_off[N_NODES] = run;
}

__global__ void k_fill_csr() {
    int e = blockIdx.x * blockDim.x + threadIdx.x;
    if (e >= N_EDGES) return;
    unsigned r = (unsigned)g_row[e];
    unsigned c = (unsigned)g_col[e];
    if (r >= N_NODES || c >= N_NODES) return;
    int pos = g_off[r] + atomicAdd(&g_cur[r], 1);
    g_ecol[pos] = (int)c;
}

// ---------------------------------------------------------------------------
// y = x @ W^T via packed f32x2 FMA.
// Block: 128 threads, 32 rows. x tile transposed in smem: xs_t[k][r],
// row stride 34 floats (even -> 8B-aligned b64 loads, pair = rows (2p,2p+1)).
// Thread (cg, pg): output cols 4cg..4cg+3, row-pairs {pg, pg+4, pg+8, pg+12}.
#define GROWS 32
#define XT_PITCH 34

__global__ void __launch_bounds__(128) k_gemm(const float* __restrict__ x) {
    __shared__ __align__(16) float xs[C * XT_PITCH];   // 17408 B

    const int tid = threadIdx.x;
    const int row0 = blockIdx.x * GROWS;
    const int nrows = min(GROWS, N_NODES - row0);

    // Load x rows coalesced, store transposed (zero-pad tail rows)
    for (int idx = tid; idx < GROWS * 32; idx += 128) {
        int r = idx >> 5, q = idx & 31;
        float4 v = make_float4(0.f, 0.f, 0.f, 0.f);
        if (r < nrows)
            v = ((const float4*)(x + (size_t)(row0 + r) * C))[q];
        xs[(4 * q + 0) * XT_PITCH + r] = v.x;
        xs[(4 * q + 1) * XT_PITCH + r] = v.y;
        xs[(4 * q + 2) * XT_PITCH + r] = v.z;
        xs[(4 * q + 3) * XT_PITCH + r] = v.w;
    }
    __syncthreads();

    const int cg = tid & 31;   // output col group: cols 4cg..4cg+3
    const int pg = tid >> 5;   // row-pair group 0..3

    unsigned long long acc[4][4];   // [pair j][col c] -> (row lo, row hi)
#pragma unroll
    for (int j = 0; j < 4; j++)
#pragma unroll
        for (int c = 0; c < 4; c++) acc[j][c] = 0ull;

    const float* wb = g_Wt + 4 * cg;
#pragma unroll 4
    for (int k = 0; k < C; k++) {
        const float4 wv = __ldg((const float4*)(wb + (size_t)k * C));
        const unsigned long long w0 = bcast2(wv.x);
        const unsigned long long w1 = bcast2(wv.y);
        const unsigned long long w2 = bcast2(wv.z);
        const unsigned long long w3 = bcast2(wv.w);
        const float* xk = xs + k * XT_PITCH;
#pragma unroll
        for (int j = 0; j < 4; j++) {
            const unsigned long long xp =
                *(const unsigned long long*)(xk + 2 * (pg + 4 * j));
            acc[j][0] = fma2(xp, w0, acc[j][0]);
            acc[j][1] = fma2(xp, w1, acc[j][1]);
            acc[j][2] = fma2(xp, w2, acc[j][2]);
            acc[j][3] = fma2(xp, w3, acc[j][3]);
        }
    }

#pragma unroll
    for (int j = 0; j < 4; j++) {
        const int pr = pg + 4 * j;
        const int r0 = 2 * pr, r1 = 2 * pr + 1;
        float4 lo, hi;
        unpack2(acc[j][0], lo.x, hi.x);
        unpack2(acc[j][1], lo.y, hi.y);
        unpack2(acc[j][2], lo.z, hi.z);
        unpack2(acc[j][3], lo.w, hi.w);
        if (r0 < nrows)
            *(float4*)(g_y + (size_t)(row0 + r0) * C + 4 * cg) = lo;
        if (r1 < nrows)
            *(float4*)(g_y + (size_t)(row0 + r1) * C + 4 * cg) = hi;
    }
}

// ---------------------------------------------------------------------------
// Warp per node: out[n] = b + dis[n] * sum_e dis[col_e] * y[col_e]
__global__ void __launch_bounds__(256) k_gather(float* __restrict__ out,
                                                const float* __restrict__ b) {
    int gtid = blockIdx.x * blockDim.x + threadIdx.x;
    int n = gtid >> 5;
    int lane = gtid & 31;
    if (n >= N_NODES) return;

    const float4 bias = __ldg(((const float4*)b) + lane);
    float ax = 0.f, ay = 0.f, az = 0.f, aw = 0.f;

    const int start = g_off[n];
    const int end = g_off[n + 1];
    const float dn = g_dis[n];

    for (int e = start; e < end; e++) {
        int c = g_ecol[e];
        float norm = dn * g_dis[c];
        float4 v = __ldg(((const float4*)(g_y + (size_t)c * C)) + lane);
        ax += norm * v.x;
        ay += norm * v.y;
        az += norm * v.z;
        aw += norm * v.w;
    }

    ((float4*)(out + (size_t)n * C))[lane] =
        make_float4(bias.x + ax, bias.y + ay, bias.z + az, bias.w + aw);
}

// ---------------------------------------------------------------------------
extern "C" void kernel_launch(void* const* d_in, const int* in_sizes, int n_in,
                              void* d_out, int out_size) {
    const float* x = (const float*)d_in[0];
    const void*  ei = d_in[1];
    const float* W = (const float*)d_in[2];
    const float* b = (const float*)d_in[3];
    float* out = (float*)d_out;

    k_detect<<<1, 256>>>((const long long*)ei);
    k_prep<<<(N_NODES + 255) / 256, 256>>>(W);
    k_edges<<<(N_EDGES + 255) / 256, 256>>>(ei);
    k_scan_fin<<<1, SCAN_T>>>();
    k_fill_csr<<<(N_EDGES + 255) / 256, 256>>>();

    k_gemm<<<(N_NODES + GROWS - 1) / GROWS, 128>>>(x);

    const long long total = (long long)N_NODES * 32;
    k_gather<<<(int)((total + 255) / 256), 256>>>(out, b);
}

// round 6
// speedup vs baseline: 1.7238x; 1.7238x over previous
#include <cuda_runtime.h>
#include <cuda_bf16.h>
#include <cstdint>

#define N_NODES 50000
#define N_EDGES 625000
#define C 128
#define NPART ((N_NODES + 255) / 256)   // 196 scan blocks

// Scratch (__device__ globals; allocations are banned)
__device__ float g_y[(size_t)N_NODES * C];   // x @ W^T
__device__ float g_dis[N_NODES];             // deg^-1/2
__device__ float g_Wt[C * C];                // W transposed: g_Wt[k*C+o] = W[o*C+k]
__device__ int   g_row[N_EDGES];
__device__ int   g_col[N_EDGES];
__device__ int   g_cnt[N_NODES];             // degree counts
__device__ int   g_cur[N_NODES];             // fill cursors
__device__ int   g_off[N_NODES + 1];         // CSR offsets
__device__ int   g_ecol[N_EDGES];            // CSR column (src) ids
__device__ int   g_part[NPART];              // scan partials
__device__ int   g_is64;

// ---------------------------------------------------------------------------
__global__ void k_detect(const long long* __restrict__ ei) {
    __shared__ int ok;
    if (threadIdx.x == 0) ok = 1;
    __syncthreads();
    for (int i = threadIdx.x; i < 1024; i += blockDim.x) {
        long long v = ei[i];
        if (v < 0 || v >= N_NODES) atomicExch(&ok, 0);
    }
    __syncthreads();
    if (threadIdx.x == 0) g_is64 = ok;
}

// zero counters + transpose W (independent work fused into one launch)
__global__ void k_prep(const float* __restrict__ W) {
    int i = blockIdx.x * blockDim.x + threadIdx.x;
    if (i < N_NODES) { g_cnt[i] = 0; g_cur[i] = 0; }
    if (i < C * C) {
        int o = i >> 7, k = i & 127;
        g_Wt[k * C + o] = W[i];
    }
}

// normalize edges + count degrees in one pass
__global__ void k_edges(const void* __restrict__ ei) {
    int e = blockIdx.x * blockDim.x + threadIdx.x;
    if (e >= N_EDGES) return;
    int r, c;
    if (g_is64) {
        const long long* p = (const long long*)ei;
        r = (int)p[e];
        c = (int)p[e + N_EDGES];
    } else {
        const int* p = (const int*)ei;
        r = p[e];
        c = p[e + N_EDGES];
    }
    g_row[e] = r;
    g_col[e] = c;
    if ((unsigned)r < N_NODES) atomicAdd(&g_cnt[r], 1);
}

// ---------------------------------------------------------------------------
// 3-phase exclusive scan of g_cnt -> g_off (full-chip, replaces 78us 1-block scan)
__global__ void __launch_bounds__(256) k_scan1() {
    __shared__ int s[256];
    const int t = threadIdx.x;
    const int i = blockIdx.x * 256 + t;
    s[t] = (i < N_NODES) ? g_cnt[i] : 0;
    __syncthreads();
#pragma unroll
    for (int off = 128; off > 0; off >>= 1) {
        if (t < off) s[t] += s[t + off];
        __syncthreads();
    }
    if (t == 0) g_part[blockIdx.x] = s[0];
}

__global__ void __launch_bounds__(256) k_scan2() {
    __shared__ int s[256];
    const int t = threadIdx.x;
    const int v = (t < NPART) ? g_part[t] : 0;
    s[t] = v;
    __syncthreads();
#pragma unroll
    for (int off = 1; off < 256; off <<= 1) {
        int u = (t >= off) ? s[t - off] : 0;
        __syncthreads();
        s[t] += u;
        __syncthreads();
    }
    if (t < NPART) g_part[t] = s[t] - v;           // exclusive
    if (t == NPART - 1) g_off[N_NODES] = s[t];     // total = N_EDGES (valid rows)
}

__global__ void __launch_bounds__(256) k_scan3() {
    __shared__ int s[256];
    const int t = threadIdx.x;
    const int i = blockIdx.x * 256 + t;
    const int v = (i < N_NODES) ? g_cnt[i] : 0;
    s[t] = v;
    __syncthreads();
#pragma unroll
    for (int off = 1; off < 256; off <<= 1) {
        int u = (t >= off) ? s[t - off] : 0;
        __syncthreads();
        s[t] += u;
        __syncthreads();
    }
    if (i < N_NODES) {
        g_off[i] = s[t] - v + g_part[blockIdx.x];
        g_dis[i] = (v > 0) ? rsqrtf((float)v) : 0.f;
    }
}

__global__ void k_fill_csr() {
    int e = blockIdx.x * blockDim.x + threadIdx.x;
    if (e >= N_EDGES) return;
    unsigned r = (unsigned)g_row[e];
    unsigned c = (unsigned)g_col[e];
    if (r >= N_NODES || c >= N_NODES) return;
    int pos = g_off[r] + atomicAdd(&g_cur[r], 1);
    g_ecol[pos] = (int)c;
}

// ---------------------------------------------------------------------------
// y = x @ W^T ; W^T (64KB) L1-resident. 32 rows/block, 128 threads. (R4-proven)
#define GROWS 32

__global__ void __launch_bounds__(128) k_gemm(const float* __restrict__ x) {
    __shared__ float xs[GROWS * C];

    const int tid = threadIdx.x;
    const int row0 = blockIdx.x * GROWS;
    const int nrows = min(GROWS, N_NODES - row0);

    for (int idx = tid; idx < GROWS * 32; idx += 128) {
        int r = idx >> 5, q = idx & 31;
        float4 v = make_float4(0.f, 0.f, 0.f, 0.f);
        if (r < nrows)
            v = ((const float4*)(x + (size_t)(row0 + r) * C))[q];
        ((float4*)(xs + r * C))[q] = v;
    }
    __syncthreads();

    const int cg = tid & 31;
    const int rg = tid >> 5;

    float acc[8][4];
#pragma unroll
    for (int i = 0; i < 8; i++)
#pragma unroll
        for (int j = 0; j < 4; j++) acc[i][j] = 0.f;

    const float* wb = g_Wt + 4 * cg;
#pragma unroll 4
    for (int k = 0; k < C; k += 4) {
        const float4 w0 = __ldg((const float4*)(wb + (size_t)(k + 0) * C));
        const float4 w1 = __ldg((const float4*)(wb + (size_t)(k + 1) * C));
        const float4 w2 = __ldg((const float4*)(wb + (size_t)(k + 2) * C));
        const float4 w3 = __ldg((const float4*)(wb + (size_t)(k + 3) * C));
#pragma unroll
        for (int r8 = 0; r8 < 8; r8++) {
            const float4 xv = *(const float4*)(xs + (rg + 4 * r8) * C + k);
            acc[r8][0] += xv.x * w0.x + xv.y * w1.x + xv.z * w2.x + xv.w * w3.x;
            acc[r8][1] += xv.x * w0.y + xv.y * w1.y + xv.z * w2.y + xv.w * w3.y;
            acc[r8][2] += xv.x * w0.z + xv.y * w1.z + xv.z * w2.z + xv.w * w3.z;
            acc[r8][3] += xv.x * w0.w + xv.y * w1.w + xv.z * w2.w + xv.w * w3.w;
        }
    }

#pragma unroll
    for (int r8 = 0; r8 < 8; r8++) {
        int r = rg + 4 * r8;
        if (r < nrows) {
            *(float4*)(g_y + (size_t)(row0 + r) * C + 4 * cg) =
                make_float4(acc[r8][0], acc[r8][1], acc[r8][2], acc[r8][3]);
        }
    }
}

// ---------------------------------------------------------------------------
// Warp per node: out[n] = b + dis[n] * sum_e dis[col_e] * y[col_e]
__global__ void __launch_bounds__(256) k_gather(float* __restrict__ out,
                                                const float* __restrict__ b) {
    int gtid = blockIdx.x * blockDim.x + threadIdx.x;
    int n = gtid >> 5;
    int lane = gtid & 31;
    if (n >= N_NODES) return;

    const float4 bias = __ldg(((const float4*)b) + lane);
    float ax = 0.f, ay = 0.f, az = 0.f, aw = 0.f;

    const int start = g_off[n];
    const int end = g_off[n + 1];
    const float dn = g_dis[n];

    for (int e = start; e < end; e++) {
        int c = g_ecol[e];
        float norm = dn * g_dis[c];
        float4 v = __ldg(((const float4*)(g_y + (size_t)c * C)) + lane);
        ax += norm * v.x;
        ay += norm * v.y;
        az += norm * v.z;
        aw += norm * v.w;
    }

    ((float4*)(out + (size_t)n * C))[lane] =
        make_float4(bias.x + ax, bias.y + ay, bias.z + az, bias.w + aw);
}

// ---------------------------------------------------------------------------
extern "C" void kernel_launch(void* const* d_in, const int* in_sizes, int n_in,
                              void* d_out, int out_size) {
    const float* x = (const float*)d_in[0];
    const void*  ei = d_in[1];
    const float* W = (const float*)d_in[2];
    const float* b = (const float*)d_in[3];
    float* out = (float*)d_out;

    k_detect<<<1, 256>>>((const long long*)ei);
    k_prep<<<(N_NODES + 255) / 256, 256>>>(W);
    k_edges<<<(N_EDGES + 255) / 256, 256>>>(ei);

    k_scan1<<<NPART, 256>>>();
    k_scan2<<<1, 256>>>();
    k_scan3<<<NPART, 256>>>();

    k_fill_csr<<<(N_EDGES + 255) / 256, 256>>>();

    k_gemm<<<(N_NODES + GROWS - 1) / GROWS, 128>>>(x);

    const long long total = (long long)N_NODES * 32;
    k_gather<<<(int)((total + 255) / 256), 256>>>(out, b);
}

// round 7
// speedup vs baseline: 1.7659x; 1.0244x over previous
#include <cuda_runtime.h>
#include <cuda_bf16.h>
#include <cstdint>

#define N_NODES 50000
#define N_EDGES 625000
#define C 128
#define NPART ((N_NODES + 255) / 256)   // 196 scan blocks

// Scratch (__device__ globals; allocations are banned)
__device__ float g_y[(size_t)N_NODES * C];   // x @ W^T
__device__ float g_dis[N_NODES];             // deg^-1/2
__device__ float g_Wt[C * C];                // W transposed: g_Wt[k*C+o] = W[o*C+k]
__device__ int   g_row[N_EDGES];
__device__ int   g_col[N_EDGES];
__device__ int   g_cnt[N_NODES];             // degree counts
__device__ int   g_cur[N_NODES];             // fill cursors
__device__ int   g_off[N_NODES + 1];         // CSR offsets
__device__ int   g_ecol[N_EDGES];            // CSR column (src) ids
__device__ int   g_part[NPART];              // scan partials
__device__ int   g_is64;

// ---------------------------------------------------------------------------
// Fused: dtype detect (block 0) + zero counters + transpose W
__global__ void k_detect_prep(const long long* __restrict__ ei,
                              const float* __restrict__ W) {
    int i = blockIdx.x * blockDim.x + threadIdx.x;
    if (i < N_NODES) { g_cnt[i] = 0; g_cur[i] = 0; }
    if (i < C * C) {
        int o = i >> 7, k = i & 127;
        g_Wt[k * C + o] = W[i];
    }
    if (blockIdx.x == 0) {
        __shared__ int ok;
        if (threadIdx.x == 0) ok = 1;
        __syncthreads();
        for (int s = threadIdx.x; s < 1024; s += blockDim.x) {
            long long v = ei[s];
            if (v < 0 || v >= N_NODES) atomicExch(&ok, 0);
        }
        __syncthreads();
        if (threadIdx.x == 0) g_is64 = ok;
    }
}

// normalize edges + count degrees in one pass
__global__ void k_edges(const void* __restrict__ ei) {
    int e = blockIdx.x * blockDim.x + threadIdx.x;
    if (e >= N_EDGES) return;
    int r, c;
    if (g_is64) {
        const long long* p = (const long long*)ei;
        r = (int)p[e];
        c = (int)p[e + N_EDGES];
    } else {
        const int* p = (const int*)ei;
        r = p[e];
        c = p[e + N_EDGES];
    }
    g_row[e] = r;
    g_col[e] = c;
    if ((unsigned)r < N_NODES) atomicAdd(&g_cnt[r], 1);
}

// ---------------------------------------------------------------------------
// Phase 1: per-block sums of g_cnt -> g_part
__global__ void __launch_bounds__(256) k_scan1() {
    __shared__ int s[256];
    const int t = threadIdx.x;
    const int i = blockIdx.x * 256 + t;
    s[t] = (i < N_NODES) ? g_cnt[i] : 0;
    __syncthreads();
#pragma unroll
    for (int off = 128; off > 0; off >>= 1) {
        if (t < off) s[t] += s[t + off];
        __syncthreads();
    }
    if (t == 0) g_part[blockIdx.x] = s[0];
}

// Phase 2+3 fused: every block scans the 196 partials itself (cheap),
// then scans its own 256 counts; writes g_off, g_dis, and (block 0) total.
__global__ void __launch_bounds__(256) k_scan_off() {
    __shared__ int sp[256];   // partial scan
    __shared__ int s[256];    // local count scan
    const int t = threadIdx.x;

    const int pv = (t < NPART) ? g_part[t] : 0;
    sp[t] = pv;
    __syncthreads();
#pragma unroll
    for (int off = 1; off < 256; off <<= 1) {
        int u = (t >= off) ? sp[t - off] : 0;
        __syncthreads();
        sp[t] += u;
        __syncthreads();
    }
    const int blk_prefix = (blockIdx.x == 0) ? 0 : sp[blockIdx.x - 1];
    if (blockIdx.x == 0 && t == 0) g_off[N_NODES] = sp[NPART - 1];

    const int i = blockIdx.x * 256 + t;
    const int v = (i < N_NODES) ? g_cnt[i] : 0;
    s[t] = v;
    __syncthreads();
#pragma unroll
    for (int off = 1; off < 256; off <<= 1) {
        int u = (t >= off) ? s[t - off] : 0;
        __syncthreads();
        s[t] += u;
        __syncthreads();
    }
    if (i < N_NODES) {
        g_off[i] = s[t] - v + blk_prefix;
        g_dis[i] = (v > 0) ? rsqrtf((float)v) : 0.f;
    }
}

__global__ void k_fill_csr() {
    int e = blockIdx.x * blockDim.x + threadIdx.x;
    if (e >= N_EDGES) return;
    unsigned r = (unsigned)g_row[e];
    unsigned c = (unsigned)g_col[e];
    if (r >= N_NODES || c >= N_NODES) return;
    int pos = g_off[r] + atomicAdd(&g_cur[r], 1);
    g_ecol[pos] = (int)c;
}

// ---------------------------------------------------------------------------
// y = x @ W^T ; W^T (64KB) L1-resident. 32 rows/block, 128 threads. (R4-proven)
#define GROWS 32

__global__ void __launch_bounds__(128) k_gemm(const float* __restrict__ x) {
    __shared__ float xs[GROWS * C];

    const int tid = threadIdx.x;
    const int row0 = blockIdx.x * GROWS;
    const int nrows = min(GROWS, N_NODES - row0);

    for (int idx = tid; idx < GROWS * 32; idx += 128) {
        int r = idx >> 5, q = idx & 31;
        float4 v = make_float4(0.f, 0.f, 0.f, 0.f);
        if (r < nrows)
            v = ((const float4*)(x + (size_t)(row0 + r) * C))[q];
        ((float4*)(xs + r * C))[q] = v;
    }
    __syncthreads();

    const int cg = tid & 31;
    const int rg = tid >> 5;

    float acc[8][4];
#pragma unroll
    for (int i = 0; i < 8; i++)
#pragma unroll
        for (int j = 0; j < 4; j++) acc[i][j] = 0.f;

    const float* wb = g_Wt + 4 * cg;
#pragma unroll 4
    for (int k = 0; k < C; k += 4) {
        const float4 w0 = __ldg((const float4*)(wb + (size_t)(k + 0) * C));
        const float4 w1 = __ldg((const float4*)(wb + (size_t)(k + 1) * C));
        const float4 w2 = __ldg((const float4*)(wb + (size_t)(k + 2) * C));
        const float4 w3 = __ldg((const float4*)(wb + (size_t)(k + 3) * C));
#pragma unroll
        for (int r8 = 0; r8 < 8; r8++) {
            const float4 xv = *(const float4*)(xs + (rg + 4 * r8) * C + k);
            acc[r8][0] += xv.x * w0.x + xv.y * w1.x + xv.z * w2.x + xv.w * w3.x;
            acc[r8][1] += xv.x * w0.y + xv.y * w1.y + xv.z * w2.y + xv.w * w3.y;
            acc[r8][2] += xv.x * w0.z + xv.y * w1.z + xv.z * w2.z + xv.w * w3.z;
            acc[r8][3] += xv.x * w0.w + xv.y * w1.w + xv.z * w2.w + xv.w * w3.w;
        }
    }

#pragma unroll
    for (int r8 = 0; r8 < 8; r8++) {
        int r = rg + 4 * r8;
        if (r < nrows) {
            *(float4*)(g_y + (size_t)(row0 + r) * C + 4 * cg) =
                make_float4(acc[r8][0], acc[r8][1], acc[r8][2], acc[r8][3]);
        }
    }
}

// ---------------------------------------------------------------------------
// Warp per node: out[n] = b + dis[n] * sum_e dis[col_e] * y[col_e]
__global__ void __launch_bounds__(256) k_gather(float* __restrict__ out,
                                                const float* __restrict__ b) {
    int gtid = blockIdx.x * blockDim.x + threadIdx.x;
    int n = gtid >> 5;
    int lane = gtid & 31;
    if (n >= N_NODES) return;

    const float4 bias = __ldg(((const float4*)b) + lane);
    float ax = 0.f, ay = 0.f, az = 0.f, aw = 0.f;

    const int start = g_off[n];
    const int end = g_off[n + 1];
    const float dn = g_dis[n];

    for (int e = start; e < end; e++) {
        int c = g_ecol[e];
        float norm = dn * g_dis[c];
        float4 v = __ldg(((const float4*)(g_y + (size_t)c * C)) + lane);
        ax += norm * v.x;
        ay += norm * v.y;
        az += norm * v.z;
        aw += norm * v.w;
    }

    ((float4*)(out + (size_t)n * C))[lane] =
        make_float4(bias.x + ax, bias.y + ay, bias.z + az, bias.w + aw);
}

// ---------------------------------------------------------------------------
extern "C" void kernel_launch(void* const* d_in, const int* in_sizes, int n_in,
                              void* d_out, int out_size) {
    const float* x = (const float*)d_in[0];
    const void*  ei = d_in[1];
    const float* W = (const float*)d_in[2];
    const float* b = (const float*)d_in[3];
    float* out = (float*)d_out;

    // Launch #4 is what the profiler captures -> put k_gemm there.
    k_detect_prep<<<(N_NODES + 255) / 256, 256>>>((const long long*)ei, W); // 1
    k_edges<<<(N_EDGES + 255) / 256, 256>>>(ei);                            // 2
    k_scan1<<<NPART, 256>>>();                                              // 3
    k_gemm<<<(N_NODES + GROWS - 1) / GROWS, 128>>>(x);                      // 4 (profiled)
    k_scan_off<<<NPART, 256>>>();                                           // 5
    k_fill_csr<<<(N_EDGES + 255) / 256, 256>>>();                           // 6
    const long long total = (long long)N_NODES * 32;
    k_gather<<<(int)((total + 255) / 256), 256>>>(out, b);                  // 7
}